// round 14
// baseline (speedup 1.0000x reference)
#include <cuda_runtime.h>
#include <cuda_fp16.h>
#include <cstdint>

// ---------------------------------------------------------------------------
// Problem constants
// ---------------------------------------------------------------------------
#define KDIM 256
#define NDIM 256
#define KC   64
#define NCHUNK (KDIM / KC)
#define M_MAX 65536

#define MAGIC   12582912.0f        /* 1.5 * 2^23 */
#define MAGIC_I 0x4B400000

// ---------------------------------------------------------------------------
// Device buffers
// ---------------------------------------------------------------------------
__device__ __align__(16) __half g_inner[M_MAX * KDIM];            // 32MB
__device__ __align__(16) unsigned char g_Bf[NCHUNK][NDIM * 128];  // swizzled B
__device__ __align__(16) unsigned char g_ctab[2432];              // padded c0c1
__device__ __align__(16) float4 g_stab[8];                        // segment cubics

// ---------------------------------------------------------------------------
// helpers
// ---------------------------------------------------------------------------
__device__ __forceinline__ uint32_t smem_u32(const void* p) {
    uint32_t a;
    asm("{ .reg .u64 t; cvta.to.shared.u64 t, %1; cvt.u32.u64 %0, t; }" : "=r"(a) : "l"(p));
    return a;
}

__device__ __forceinline__ void ldsm_x4(uint32_t& r0, uint32_t& r1, uint32_t& r2,
                                        uint32_t& r3, uint32_t addr) {
    asm volatile("ldmatrix.sync.aligned.m8n8.x4.shared.b16 {%0,%1,%2,%3}, [%4];"
                 : "=r"(r0), "=r"(r1), "=r"(r2), "=r"(r3) : "r"(addr));
}

__device__ __forceinline__ void mma_fp16(float* c, const uint32_t* a,
                                         uint32_t b0, uint32_t b1) {
    asm volatile(
        "mma.sync.aligned.m16n8k16.row.col.f32.f16.f16.f32 "
        "{%0,%1,%2,%3}, {%4,%5,%6,%7}, {%8,%9}, {%0,%1,%2,%3};"
        : "+f"(c[0]), "+f"(c[1]), "+f"(c[2]), "+f"(c[3])
        : "r"(a[0]), "r"(a[1]), "r"(a[2]), "r"(a[3]), "r"(b0), "r"(b1));
}

#define CP_ASYNC16(saddr, gptr) \
    asm volatile("cp.async.cg.shared.global [%0], [%1], 16;" :: "r"(saddr), "l"(gptr))
#define CP_COMMIT() asm volatile("cp.async.commit_group;")
#define CP_WAIT0()  asm volatile("cp.async.wait_group 0;")
#define CP_WAIT1()  asm volatile("cp.async.wait_group 1;")

__device__ __forceinline__ uint32_t pack_h2(float a0, float a1) {
    __half2 h = __floats2half2_rn(a0, a1);
    return *reinterpret_cast<uint32_t*>(&h);
}

__device__ __host__ __forceinline__ int ctab_off(int k) {
    return k * 8 + (k >> 4) * 16;
}

// ---------------------------------------------------------------------------
// Prologue: fp16 pre-swizzled B images + c0c1 pairs + segment-cubic table
// ---------------------------------------------------------------------------
__global__ void kan_prologue(const float* __restrict__ ic, const float* __restrict__ oc) {
    if (blockIdx.x < 32) {
        int gid = blockIdx.x * 256 + threadIdx.x;   // 0..8191
        int n   = gid >> 5;                          // B row 0..255
        int g   = gid & 31;                          // k-granule (8 fp32)
        int chunk = g >> 3;
        int colg  = g & 7;
        const float4* src = (const float4*)(oc + n * KDIM + g * 8);
        float4 v0 = src[0], v1 = src[1];
        float a[8] = {v0.x, v0.y, v0.z, v0.w, v1.x, v1.y, v1.z, v1.w};
        uint32_t h[4];
#pragma unroll
        for (int e = 0; e < 4; e++) h[e] = pack_h2(a[2 * e], a[2 * e + 1]);
        int off = n * 128 + ((colg ^ (n & 7)) << 4);
        *(uint4*)(g_Bf[chunk] + off) = make_uint4(h[0], h[1], h[2], h[3]);
    } else {
        int k = threadIdx.x;
        float c0 = ic[k * 5 + 0];
        float c1 = ic[k * 5 + 1];
        *(float2*)(g_ctab + ctab_off(k)) = make_float2(c0, c1);
        if (k < 8) {
            const float P[4][4] = {
                {0.f, 0.f, 0.f,  1.f},
                {1.f, 3.f, 3.f, -3.f},
                {4.f, 0.f, -6.f, 3.f},
                {1.f, -3.f, 3.f, -1.f}
            };
            float4 s = make_float4(0.f, 0.f, 0.f, 0.f);
            if (k >= 1 && k <= 4) {
                const float s6 = 1.0f / 6.0f;
                int m = k - 1;
                s = make_float4(P[m][0] * s6, P[m][1] * s6, P[m][2] * s6, P[m][3] * s6);
            }
            g_stab[k] = s;
        }
    }
}

// ---------------------------------------------------------------------------
// Validated activation (R13): v = 7 - 7/(e^{2x}+1); magic floor; seg cubics
// ---------------------------------------------------------------------------
__device__ __forceinline__ float kan_act2(float xv, float c0, float c1,
                                          const float4* __restrict__ stab) {
    float e2 = __expf(2.0f * xv);
    float v  = 7.0f - __fdividef(7.0f, e2 + 1.0f);   // in (0,7)
    float wf = __fadd_rz(v, MAGIC);
    int   j  = __float_as_int(wf) - MAGIC_I;
    float jf = wf - MAGIC;
    j  = j > 5 ? 5 : j;
    jf = fminf(jf, 5.0f);
    float u = v - jf;
    float4 sB = stab[j];
    float4 sA = stab[j + 1];
    float b30 = fmaf(fmaf(fmaf(sA.w, u, sA.z), u, sA.y), u, sA.x);
    float b31 = fmaf(fmaf(fmaf(sB.w, u, sB.z), u, sB.y), u, sB.x);
    return fmaf(c0, b30, c1 * b31);
}

__device__ __forceinline__ void act16(const float* av, int kb, const char* ctab,
                                      const float4* __restrict__ stab, float* r) {
#pragma unroll
    for (int p = 0; p < 8; p++) {
        int k0 = kb + 2 * p;
        float4 cg = *(const float4*)(ctab + ctab_off(k0));
        r[2 * p]     = kan_act2(av[2 * p],     cg.x, cg.y, stab);
        r[2 * p + 1] = kan_act2(av[2 * p + 1], cg.z, cg.w, stab);
    }
}

// ---------------------------------------------------------------------------
// Kernel 1: streaming activation  x(fp32) -> inner(fp16, row-major)
// thread = (row, kq): 16 consecutive k elements
// ---------------------------------------------------------------------------
__global__ void __launch_bounds__(256)
kan_act_kernel(const float* __restrict__ x) {
    __shared__ __align__(16) float4 s_stab[8];
    __shared__ __align__(16) char s_ctab[2432];
    const int tid = threadIdx.x;
    if (tid < 160) {
        if (tid < 8) s_stab[tid] = g_stab[tid];
        else ((float4*)s_ctab)[tid - 8] = ((const float4*)g_ctab)[tid - 8];
    }
    __syncthreads();

    const int gid = blockIdx.x * 256 + tid;
    const int row = gid >> 4;
    const int kq  = gid & 15;

    const float4* xp = (const float4*)(x + (size_t)row * KDIM + kq * 16);
    float4 xv0 = xp[0], xv1 = xp[1], xv2 = xp[2], xv3 = xp[3];
    float av[16] = {xv0.x, xv0.y, xv0.z, xv0.w, xv1.x, xv1.y, xv1.z, xv1.w,
                    xv2.x, xv2.y, xv2.z, xv2.w, xv3.x, xv3.y, xv3.z, xv3.w};
    float r[16];
    act16(av, kq * 16, s_ctab, s_stab, r);

    uint4* op = (uint4*)(g_inner + (size_t)row * KDIM + kq * 16);
    op[0] = make_uint4(pack_h2(r[0], r[1]),   pack_h2(r[2], r[3]),
                       pack_h2(r[4], r[5]),   pack_h2(r[6], r[7]));
    op[1] = make_uint4(pack_h2(r[8], r[9]),   pack_h2(r[10], r[11]),
                       pack_h2(r[12], r[13]), pack_h2(r[14], r[15]));
}

// ---------------------------------------------------------------------------
// Kernel 2: pure fp16 HMMA GEMM  out[M,256] = inner[M,256] @ W^T
// CTA tile 128x128; 3-stage cp.async ring over 4 K-chunks.
// ---------------------------------------------------------------------------
#define ST_A(s) ((s) * 32768)
#define ST_B(s) ((s) * 32768 + 16384)
#define K2_SMEM (3 * 32768)          // 98304

__global__ void __launch_bounds__(256, 2)
kan_gemm(float* __restrict__ out) {
    extern __shared__ __align__(1024) char smem[];
    const uint32_t sbase = smem_u32(smem);
    const int tid = threadIdx.x;
    const int wid = tid >> 5;
    const int lid = tid & 31;
    const int m0 = (blockIdx.x >> 1) * 128;
    const int n0 = (blockIdx.x & 1) * 128;

    // warp tile 32(M) x 64(N): 4 M-warps x 2 N-warps
    const int wm = (wid >> 1) * 32;
    const int wn = (wid & 1) * 64;

    const __half* innerBase = g_inner + (size_t)m0 * KDIM;

    // issue chunk c into stage s (A swizzled from row-major, B pre-swizzled)
    auto issue = [&](int c, int s) {
#pragma unroll
        for (int i = 0; i < 4; i++) {                 // A: 1024 granules
            int idx = tid + i * 256;
            int r = idx >> 3, g = idx & 7;
            const char* src = (const char*)(innerBase + (size_t)r * KDIM + c * KC) + g * 16;
            uint32_t dst = sbase + ST_A(s) + r * 128 + ((g ^ (r & 7)) << 4);
            CP_ASYNC16(dst, src);
        }
        const char* bsrc = (const char*)g_Bf[c] + n0 * 128;
#pragma unroll
        for (int i = 0; i < 4; i++) {                 // B: 1024 granules
            int idx = tid + i * 256;
            CP_ASYNC16(sbase + ST_B(s) + idx * 16, bsrc + idx * 16);
        }
        CP_COMMIT();
    };

    issue(0, 0);
    issue(1, 1);

    float acc[2][8][4];
#pragma unroll
    for (int mt = 0; mt < 2; mt++)
#pragma unroll
        for (int nt = 0; nt < 8; nt++)
#pragma unroll
            for (int e = 0; e < 4; e++) acc[mt][nt][e] = 0.0f;

    const int lr   = lid & 15;
    const int lhal = lid >> 4;

#pragma unroll
    for (int c = 0; c < NCHUNK; c++) {
        if (c < 3) { CP_WAIT1(); } else { CP_WAIT0(); }   // chunk c landed
        __syncthreads();            // all warps done MMA(c-1); stage (c+2)%3 free
        if (c < 2) issue(c + 2, (c + 2) % 3);

        const uint32_t aBase = sbase + ST_A(c % 3);
        const uint32_t bBase = sbase + ST_B(c % 3);
#pragma unroll
        for (int ks = 0; ks < 4; ks++) {
            const int g = ks * 2 + lhal;
            uint32_t a[2][4];
#pragma unroll
            for (int mt = 0; mt < 2; mt++) {
                int r = wm + mt * 16 + lr;
                uint32_t off = (uint32_t)(r * 128 + ((g ^ (r & 7)) << 4));
                ldsm_x4(a[mt][0], a[mt][1], a[mt][2], a[mt][3], aBase + off);
            }
#pragma unroll
            for (int np = 0; np < 4; np++) {
                int r = wn + np * 16 + lr;
                uint32_t off = (uint32_t)(r * 128 + ((g ^ (r & 7)) << 4));
                uint32_t b[4];
                ldsm_x4(b[0], b[1], b[2], b[3], bBase + off);
#pragma unroll
                for (int mt = 0; mt < 2; mt++) {
                    mma_fp16(acc[mt][2 * np + 0], a[mt], b[0], b[2]);
                    mma_fp16(acc[mt][2 * np + 1], a[mt], b[1], b[3]);
                }
            }
        }
    }

    // epilogue
    {
        const int rq = lid >> 2;
        const int cq = (lid & 3) * 2;
#pragma unroll
        for (int mt = 0; mt < 2; mt++) {
            int row = m0 + wm + mt * 16 + rq;
#pragma unroll
            for (int nt = 0; nt < 8; nt++) {
                int col = n0 + wn + nt * 8 + cq;
                float2 v0 = make_float2(acc[mt][nt][0], acc[mt][nt][1]);
                float2 v1 = make_float2(acc[mt][nt][2], acc[mt][nt][3]);
                *(float2*)(out + (size_t)row * NDIM + col)       = v0;
                *(float2*)(out + (size_t)(row + 8) * NDIM + col) = v1;
            }
        }
    }
}

// ---------------------------------------------------------------------------
extern "C" void kernel_launch(void* const* d_in, const int* in_sizes, int n_in,
                              void* d_out, int out_size) {
    const float* x  = (const float*)d_in[0];   // [B,S,256] fp32
    const float* ic = (const float*)d_in[1];   // [256,5]   fp32
    const float* oc = (const float*)d_in[2];   // [256,256] fp32
    float* out = (float*)d_out;

    const int M = in_sizes[0] / KDIM;          // 65536

    cudaFuncSetAttribute(kan_gemm, cudaFuncAttributeMaxDynamicSharedMemorySize, K2_SMEM);

    kan_prologue<<<33, 256>>>(ic, oc);
    kan_act_kernel<<<M / 16, 256>>>(x);        // M*16 threads
    kan_gemm<<<(M / 128) * 2, 256, K2_SMEM>>>(out);
}

// round 15
// speedup vs baseline: 1.0299x; 1.0299x over previous
#include <cuda_runtime.h>
#include <cuda_fp16.h>
#include <cstdint>

// ---------------------------------------------------------------------------
// Problem constants
// ---------------------------------------------------------------------------
#define KDIM 256
#define NDIM 256
#define KC   64
#define NCHUNK (KDIM / KC)
#define M_MAX 65536
#define BM 64                       // gemm CTA M tile

#define MAGIC   12582912.0f         /* 1.5 * 2^23 */
#define MAGIC_I 0x4B400000

// ---------------------------------------------------------------------------
// Device buffers
// ---------------------------------------------------------------------------
__device__ __align__(16) __half g_inner[M_MAX * KDIM];            // 32MB
__device__ __align__(16) unsigned char g_Bf[NCHUNK][NDIM * 128];  // swizzled B

// ---------------------------------------------------------------------------
// helpers
// ---------------------------------------------------------------------------
__device__ __forceinline__ uint32_t smem_u32(const void* p) {
    uint32_t a;
    asm("{ .reg .u64 t; cvta.to.shared.u64 t, %1; cvt.u32.u64 %0, t; }" : "=r"(a) : "l"(p));
    return a;
}

__device__ __forceinline__ void ldsm_x4(uint32_t& r0, uint32_t& r1, uint32_t& r2,
                                        uint32_t& r3, uint32_t addr) {
    asm volatile("ldmatrix.sync.aligned.m8n8.x4.shared.b16 {%0,%1,%2,%3}, [%4];"
                 : "=r"(r0), "=r"(r1), "=r"(r2), "=r"(r3) : "r"(addr));
}

__device__ __forceinline__ void mma_fp16(float* c, const uint32_t* a,
                                         uint32_t b0, uint32_t b1) {
    asm volatile(
        "mma.sync.aligned.m16n8k16.row.col.f32.f16.f16.f32 "
        "{%0,%1,%2,%3}, {%4,%5,%6,%7}, {%8,%9}, {%0,%1,%2,%3};"
        : "+f"(c[0]), "+f"(c[1]), "+f"(c[2]), "+f"(c[3])
        : "r"(a[0]), "r"(a[1]), "r"(a[2]), "r"(a[3]), "r"(b0), "r"(b1));
}

#define CP_ASYNC16(saddr, gptr) \
    asm volatile("cp.async.cg.shared.global [%0], [%1], 16;" :: "r"(saddr), "l"(gptr))
#define CP_COMMIT() asm volatile("cp.async.commit_group;")
#define CP_WAIT0()  asm volatile("cp.async.wait_group 0;")

__device__ __forceinline__ uint32_t pack_h2(float a0, float a1) {
    __half2 h = __floats2half2_rn(a0, a1);
    return *reinterpret_cast<uint32_t*>(&h);
}

__device__ __host__ __forceinline__ int ctab_off(int k) {
    return k * 8 + (k >> 4) * 16;
}

// ---------------------------------------------------------------------------
// Activation: v = 7 - 7/(e^{2x}+1) in (0,7); exact magic floor; seg cubics.
// j in 0..6 naturally (min(j,6) guards e2=inf); stab[0]=stab[5..7]=0.
// ---------------------------------------------------------------------------
__device__ __forceinline__ float kan_act2(float xv, float c0, float c1,
                                          const float4* __restrict__ stab) {
    float e2 = __expf(2.0f * xv);
    float v  = 7.0f - __fdividef(7.0f, e2 + 1.0f);
    float wf = __fadd_rz(v, MAGIC);
    int   j  = __float_as_int(wf) - MAGIC_I;
    j = j > 6 ? 6 : j;
    float u  = v - (wf - MAGIC);
    float4 sB = stab[j];        // B31 segment cubic
    float4 sA = stab[j + 1];    // B30 segment cubic
    float b30 = fmaf(fmaf(fmaf(sA.w, u, sA.z), u, sA.y), u, sA.x);
    float b31 = fmaf(fmaf(fmaf(sB.w, u, sB.z), u, sB.y), u, sB.x);
    return fmaf(c0, b30, c1 * b31);
}

__device__ __forceinline__ void act16(const float* av, int kb, const char* ctab,
                                      const float4* __restrict__ stab, float* r) {
#pragma unroll
    for (int p = 0; p < 8; p++) {
        int k0 = kb + 2 * p;
        float4 cg = *(const float4*)(ctab + ctab_off(k0));
        r[2 * p]     = kan_act2(av[2 * p],     cg.x, cg.y, stab);
        r[2 * p + 1] = kan_act2(av[2 * p + 1], cg.z, cg.w, stab);
    }
}

// ---------------------------------------------------------------------------
// Kernel 1: activation  x(fp32) -> g_inner(fp16, row-major).
// Tables built in-block (no prologue); blocks 0..31 also build g_Bf.
// ---------------------------------------------------------------------------
__global__ void __launch_bounds__(256)
kan_act_kernel(const float* __restrict__ x, const float* __restrict__ ic,
               const float* __restrict__ oc) {
    __shared__ __align__(16) float4 s_stab[8];
    __shared__ __align__(16) char s_ctab[2432];
    const int tid = threadIdx.x;

    // build stab (bit-identical arithmetic to previous prologue)
    if (tid < 8) {
        const float P[4][4] = {
            {0.f, 0.f, 0.f,  1.f},
            {1.f, 3.f, 3.f, -3.f},
            {4.f, 0.f, -6.f, 3.f},
            {1.f, -3.f, 3.f, -1.f}
        };
        float4 s = make_float4(0.f, 0.f, 0.f, 0.f);
        if (tid >= 1 && tid <= 4) {
            const float s6 = 1.0f / 6.0f;
            int m = tid - 1;
            s = make_float4(P[m][0] * s6, P[m][1] * s6, P[m][2] * s6, P[m][3] * s6);
        }
        s_stab[tid] = s;
    }
    // build ctab straight from ic (5KB, L2-hot)
    if (tid < 128) {
        int q = tid;                         // granule: channels 2q, 2q+1
        float c0a = __ldg(&ic[10 * q + 0]);
        float c1a = __ldg(&ic[10 * q + 1]);
        float c0b = __ldg(&ic[10 * q + 5]);
        float c1b = __ldg(&ic[10 * q + 6]);
        *(float4*)(s_ctab + 16 * q + 16 * (q >> 3)) = make_float4(c0a, c1a, c0b, c1b);
    }
    __syncthreads();

    // ---- act: 16 elements per thread ----
    const int gid = blockIdx.x * 256 + tid;
    const int row = gid >> 4;
    const int kq  = gid & 15;

    const float4* xp = (const float4*)(x + (size_t)row * KDIM + kq * 16);
    float4 xv0 = xp[0], xv1 = xp[1], xv2 = xp[2], xv3 = xp[3];
    float av[16] = {xv0.x, xv0.y, xv0.z, xv0.w, xv1.x, xv1.y, xv1.z, xv1.w,
                    xv2.x, xv2.y, xv2.z, xv2.w, xv3.x, xv3.y, xv3.z, xv3.w};
    float r[16];
    act16(av, kq * 16, s_ctab, s_stab, r);

    uint4* op = (uint4*)(g_inner + (size_t)row * KDIM + kq * 16);
    op[0] = make_uint4(pack_h2(r[0], r[1]),   pack_h2(r[2], r[3]),
                       pack_h2(r[4], r[5]),   pack_h2(r[6], r[7]));
    op[1] = make_uint4(pack_h2(r[8], r[9]),   pack_h2(r[10], r[11]),
                       pack_h2(r[12], r[13]), pack_h2(r[14], r[15]));

    // ---- blocks 0..31: build pre-swizzled fp16 B images (before gemm launch) ----
    if (blockIdx.x < 32) {
        int bgid = blockIdx.x * 256 + tid;          // 0..8191
        int n    = bgid >> 5;                        // B row 0..255
        int g    = bgid & 31;                        // k-granule (8 fp32)
        int chunk = g >> 3;
        int colg  = g & 7;
        const float4* src = (const float4*)(oc + n * KDIM + g * 8);
        float4 v0 = src[0], v1 = src[1];
        float a[8] = {v0.x, v0.y, v0.z, v0.w, v1.x, v1.y, v1.z, v1.w};
        uint32_t h[4];
#pragma unroll
        for (int e = 0; e < 4; e++) h[e] = pack_h2(a[2 * e], a[2 * e + 1]);
        int off = n * 128 + ((colg ^ (n & 7)) << 4);
        *(uint4*)(g_Bf[chunk] + off) = make_uint4(h[0], h[1], h[2], h[3]);
    }
}

// ---------------------------------------------------------------------------
// Kernel 2: pure fp16 HMMA GEMM  out[M,256] = g_inner[M,256] @ W^T
// R10 shape: BM=64, N=256, 8 warps (2Mx4N, 32x64), 2 CTAs/SM, dbuf cp.async.
// ---------------------------------------------------------------------------
#define ST_A(s) ((s) * 40960)
#define ST_B(s) ((s) * 40960 + 8192)
#define K2_SMEM (2 * 40960)          // 81920 -> 2 CTAs/SM

__global__ void __launch_bounds__(256, 2)
kan_gemm(float* __restrict__ out) {
    extern __shared__ __align__(1024) char smem[];
    const uint32_t sbase = smem_u32(smem);
    const int tid = threadIdx.x;
    const int wid = tid >> 5;
    const int lid = tid & 31;
    const int m0  = blockIdx.x * BM;

    const int wm = (wid >> 2) * 32;      // 2 M-warps
    const int wn = (wid & 3) * 64;       // 4 N-warps

    const char* innerBase = (const char*)(g_inner + (size_t)m0 * KDIM);

    // issue chunk c into stage s: A (swizzle on the fly) + B (pre-swizzled)
    auto issue = [&](int c, int s) {
#pragma unroll
        for (int i = 0; i < 2; i++) {                 // A: 512 granules
            int idx = tid + i * 256;
            int r = idx >> 3, g = idx & 7;
            const char* src = innerBase + (size_t)r * 512 + c * 128 + g * 16;
            uint32_t dst = sbase + ST_A(s) + r * 128 + ((g ^ (r & 7)) << 4);
            CP_ASYNC16(dst, src);
        }
        const char* bsrc = (const char*)g_Bf[c];
#pragma unroll
        for (int i = 0; i < 8; i++) {                 // B: 2048 granules
            int idx = tid + i * 256;
            CP_ASYNC16(sbase + ST_B(s) + idx * 16, bsrc + idx * 16);
        }
        CP_COMMIT();
    };

    issue(0, 0);

    float acc[2][8][4];
#pragma unroll
    for (int mt = 0; mt < 2; mt++)
#pragma unroll
        for (int nt = 0; nt < 8; nt++)
#pragma unroll
            for (int e = 0; e < 4; e++) acc[mt][nt][e] = 0.0f;

    const int lr   = lid & 15;
    const int lhal = lid >> 4;

#pragma unroll
    for (int c = 0; c < NCHUNK; c++) {
        const int s = c & 1;
        CP_WAIT0();                      // chunk c landed (one group in flight)
        __syncthreads();                 // visible to all; stage s^1 readers done

        if (c < NCHUNK - 1) issue(c + 1, s ^ 1);   // hidden under MMA(c)

        const uint32_t aBase = sbase + ST_A(s);
        const uint32_t bBase = sbase + ST_B(s);
#pragma unroll
        for (int ks = 0; ks < 4; ks++) {
            const int g = ks * 2 + lhal;
            uint32_t a[2][4];
#pragma unroll
            for (int mt = 0; mt < 2; mt++) {
                int r = wm + mt * 16 + lr;
                uint32_t off = (uint32_t)(r * 128 + ((g ^ (r & 7)) << 4));
                ldsm_x4(a[mt][0], a[mt][1], a[mt][2], a[mt][3], aBase + off);
            }
#pragma unroll
            for (int np = 0; np < 4; np++) {
                int r = wn + np * 16 + lr;
                uint32_t off = (uint32_t)(r * 128 + ((g ^ (r & 7)) << 4));
                uint32_t b[4];
                ldsm_x4(b[0], b[1], b[2], b[3], bBase + off);
#pragma unroll
                for (int mt = 0; mt < 2; mt++) {
                    mma_fp16(acc[mt][2 * np + 0], a[mt], b[0], b[2]);
                    mma_fp16(acc[mt][2 * np + 1], a[mt], b[1], b[3]);
                }
            }
        }
    }

    // epilogue
    {
        const int rq = lid >> 2;
        const int cq = (lid & 3) * 2;
#pragma unroll
        for (int mt = 0; mt < 2; mt++) {
            int row = m0 + wm + mt * 16 + rq;
#pragma unroll
            for (int nt = 0; nt < 8; nt++) {
                int col = wn + nt * 8 + cq;
                float2 v0 = make_float2(acc[mt][nt][0], acc[mt][nt][1]);
                float2 v1 = make_float2(acc[mt][nt][2], acc[mt][nt][3]);
                *(float2*)(out + (size_t)row * NDIM + col)       = v0;
                *(float2*)(out + (size_t)(row + 8) * NDIM + col) = v1;
            }
        }
    }
}

// ---------------------------------------------------------------------------
extern "C" void kernel_launch(void* const* d_in, const int* in_sizes, int n_in,
                              void* d_out, int out_size) {
    const float* x  = (const float*)d_in[0];   // [B,S,256] fp32
    const float* ic = (const float*)d_in[1];   // [256,5]   fp32
    const float* oc = (const float*)d_in[2];   // [256,256] fp32
    float* out = (float*)d_out;

    const int M = in_sizes[0] / KDIM;          // 65536

    cudaFuncSetAttribute(kan_gemm, cudaFuncAttributeMaxDynamicSharedMemorySize, K2_SMEM);

    kan_act_kernel<<<M / 16, 256>>>(x, ic, oc);       // act + B-prep (blocks<32)
    kan_gemm<<<M / BM, 256, K2_SMEM>>>(out);
}